// round 1
// baseline (speedup 1.0000x reference)
#include <cuda_runtime.h>
#include <math.h>

#define NN 3000
#define EE 48000
#define FF 32
#define BM_WORDS 281250   // ceil(3000*3000/32)
#define NPAD 4096
#define EXCL 1200
#define KSEL 10800.0f

// ---------------- static device scratch (no allocations allowed) ----------------
__device__ unsigned int g_bitmap[BM_WORDS];
__device__ int   g_deg[NN];
__device__ int   g_ucnt[NN];
__device__ int   g_rowptr[NN + 1];
__device__ int   g_cursor[NN];
__device__ unsigned char g_keep[EE];
__device__ int   g_colidx[EE];
__device__ float g_wv[EE];        // invD[col] per CSR entry (J weights)
__device__ float g_sinv[NN];      // 1/(deg - alpha)
__device__ float g_invD[NN];      // 1/((deg - alpha)*h)
// buffers: 0=X1, 1=X2, 2=Y1, 3=Y2, 4=BJ, 5=TA, 6=TB
__device__ float g_bufs[7][NN * FF];

// ---------------- setup kernels ----------------
__global__ void k_zero() {
    int i = blockIdx.x * blockDim.x + threadIdx.x;
    if (i < BM_WORDS) g_bitmap[i] = 0u;
    if (i < NN) { g_deg[i] = 0; g_ucnt[i] = 0; }
}

__global__ void k_edges(const int* __restrict__ row, const int* __restrict__ col) {
    int e = blockIdx.x * blockDim.x + threadIdx.x;
    if (e >= EE) return;
    int r = row[e], c = col[e];
    atomicAdd(&g_deg[r], 1);                       // degree WITH multiplicity (reference .add)
    unsigned int bitpos = (unsigned int)(r * NN + c);
    unsigned int w = bitpos >> 5, b = 1u << (bitpos & 31);
    unsigned int old = atomicOr(&g_bitmap[w], b);  // dedup (reference .set)
    unsigned char keep = (old & b) ? 0 : 1;
    g_keep[e] = keep;
    if (keep) atomicAdd(&g_ucnt[r], 1);
}

// single-block scan of unique counts -> rowptr/cursor, plus per-node scalars
__global__ void k_scan(const float* __restrict__ ph, const float* __restrict__ palpha) {
    __shared__ int loc[3072];
    __shared__ int part[1024];
    int tid = threadIdx.x;
    float h = *ph, alpha = *palpha;

    for (int i = tid; i < NN; i += 1024) loc[i] = g_ucnt[i];
    for (int i = NN + tid; i < 3072; i += 1024) loc[i] = 0;
    __syncthreads();

    int base = 3 * tid;
    int a0 = loc[base], a1 = loc[base + 1], a2 = loc[base + 2];
    part[tid] = a0 + a1 + a2;
    __syncthreads();
    for (int off = 1; off < 1024; off <<= 1) {
        int v = part[tid];
        int add = (tid >= off) ? part[tid - off] : 0;
        __syncthreads();
        part[tid] = v + add;
        __syncthreads();
    }
    int excl = (tid == 0) ? 0 : part[tid - 1];
    if (base < NN)     { g_rowptr[base]     = excl;           g_cursor[base]     = excl; }
    if (base + 1 < NN) { g_rowptr[base + 1] = excl + a0;      g_cursor[base + 1] = excl + a0; }
    if (base + 2 < NN) { g_rowptr[base + 2] = excl + a0 + a1; g_cursor[base + 2] = excl + a0 + a1; }
    if (tid == 1023)     g_rowptr[NN] = part[1023];

    for (int i = tid; i < NN; i += 1024) {
        float dv = (float)g_deg[i] - alpha;
        g_sinv[i] = 1.0f / dv;
        g_invD[i] = 1.0f / (dv * h);
    }
}

__global__ void k_scatter(const int* __restrict__ row, const int* __restrict__ col) {
    int e = blockIdx.x * blockDim.x + threadIdx.x;
    if (e >= EE) return;
    if (!g_keep[e]) return;
    int r = row[e], c = col[e];
    int pos = atomicAdd(&g_cursor[r], 1);
    g_colidx[pos] = c;
    g_wv[pos] = g_invD[c];
}

// ---------------- conv kernels (warp per row, lane per feature) ----------------
// b_j = y - sinv[i] * (A y)[i]
__global__ void k_bjac(const float* __restrict__ ext, int in_sel, int out_sel) {
    const float* __restrict__ yin = (in_sel >= 0) ? g_bufs[in_sel] : ext;
    float* __restrict__ out = g_bufs[out_sel];
    int rowi = blockIdx.x * 8 + (threadIdx.x >> 5);
    int lane = threadIdx.x & 31;
    if (rowi >= NN) return;
    int p0 = g_rowptr[rowi], p1 = g_rowptr[rowi + 1];
    float acc = 0.f;
    for (int p = p0; p < p1; ++p) {
        int c = g_colidx[p];
        acc += yin[c * FF + lane];
    }
    out[rowi * FF + lane] = yin[rowi * FF + lane] - g_sinv[rowi] * acc;
}

// yk_new = (J yk)[i] + b_j[i], J weights prefolded into g_wv
__global__ void k_jac(int yk_sel, int bj_sel, int out_sel) {
    const float* __restrict__ yk = g_bufs[yk_sel];
    const float* __restrict__ bj = g_bufs[bj_sel];
    float* __restrict__ out = g_bufs[out_sel];
    int rowi = blockIdx.x * 8 + (threadIdx.x >> 5);
    int lane = threadIdx.x & 31;
    if (rowi >= NN) return;
    int p0 = g_rowptr[rowi], p1 = g_rowptr[rowi + 1];
    float acc = 0.f;
    for (int p = p0; p < p1; ++p) {
        int c = g_colidx[p];
        acc += g_wv[p] * yk[c * FF + lane];
    }
    out[rowi * FF + lane] = acc + bj[rowi * FF + lane];
}

// Xout = relu( X Wr^T + 2 Y1 Wca^T + 2 Y2 Wcb^T )   (Y1=bufs[2], Y2=bufs[3])
__global__ void k_outgemm(const float* __restrict__ ext, int in_sel,
                          const float* __restrict__ Wr, const float* __restrict__ Wa,
                          const float* __restrict__ Wb, int out_sel) {
    __shared__ float sWr[FF * FF], sWa[FF * FF], sWb[FF * FF];
    const float* __restrict__ X = (in_sel >= 0) ? g_bufs[in_sel] : ext;
    const float* __restrict__ Y1 = g_bufs[2];
    const float* __restrict__ Y2 = g_bufs[3];
    float* __restrict__ out = g_bufs[out_sel];
    for (int t = threadIdx.x; t < FF * FF; t += blockDim.x) {
        int f = t >> 5, k = t & 31;           // source W[f][k] -> transposed store
        sWr[k * FF + f] = Wr[t];
        sWa[k * FF + f] = Wa[t];
        sWb[k * FF + f] = Wb[t];
    }
    __syncthreads();
    int rowi = blockIdx.x * 8 + (threadIdx.x >> 5);
    int lane = threadIdx.x & 31;
    if (rowi >= NN) return;
    float xo  = X[rowi * FF + lane];
    float y1o = Y1[rowi * FF + lane];
    float y2o = Y2[rowi * FF + lane];
    float acc = 0.f;
#pragma unroll
    for (int k = 0; k < FF; ++k) {
        float xv  = __shfl_sync(0xffffffffu, xo, k);
        float y1v = __shfl_sync(0xffffffffu, y1o, k);
        float y2v = __shfl_sync(0xffffffffu, y2o, k);
        acc += xv * sWr[k * FF + lane]
             + 2.0f * y1v * sWa[k * FF + lane]
             + 2.0f * y2v * sWb[k * FF + lane];
    }
    out[rowi * FF + lane] = fmaxf(acc, 0.0f);
}

// ---------------- finale: scores, bitonic top-k exclusion, pooled linear ----------------
__device__ __forceinline__ unsigned int f2ord(float f) {
    unsigned int u = __float_as_uint(f);
    return (u & 0x80000000u) ? ~u : (u | 0x80000000u);
}

__global__ void k_final(const float* __restrict__ pw, const float* __restrict__ lw,
                        const float* __restrict__ lb, float* __restrict__ out) {
    __shared__ unsigned long long keys[NPAD];   // 32 KB, reused as float scratch later
    __shared__ float sc[3008];
    __shared__ float sg[FF];
    const float* __restrict__ X2 = g_bufs[1];
    int tid = threadIdx.x;
    int w = tid >> 5, lane = tid & 31;

    // per-warp norm of pool_w (32 elems)
    float pwv = pw[lane];
    float nv = pwv * pwv;
#pragma unroll
    for (int o = 16; o > 0; o >>= 1) nv += __shfl_xor_sync(0xffffffffu, nv, o);
    float norm = sqrtf(nv);

    // scores + sort keys (value asc, equal values: larger index first = excluded first)
    for (int i = w; i < NN; i += 32) {
        float v = X2[i * FF + lane] * pwv;
#pragma unroll
        for (int o = 16; o > 0; o >>= 1) v += __shfl_xor_sync(0xffffffffu, v, o);
        float s = tanhf(v / norm);
        if (lane == 0) {
            sc[i] = s;
            keys[i] = ((unsigned long long)f2ord(s) << 32)
                    | (unsigned long long)(0xFFFFFFFFu - (unsigned int)i);
        }
    }
    for (int i = NN + tid; i < NPAD; i += 1024) keys[i] = 0xFFFFFFFFFFFFFFFFull;
    __syncthreads();

    // bitonic sort ascending, 4096 keys
    for (unsigned int kk = 2; kk <= NPAD; kk <<= 1) {
        for (unsigned int j = kk >> 1; j > 0; j >>= 1) {
            for (unsigned int i = tid; i < NPAD; i += 1024) {
                unsigned int ixj = i ^ j;
                if (ixj > i) {
                    bool up = ((i & kk) == 0);
                    unsigned long long a = keys[i], b = keys[ixj];
                    if (up ? (a > b) : (a < b)) { keys[i] = b; keys[ixj] = a; }
                }
            }
            __syncthreads();
        }
    }

    // exclude: first 1200 sorted entries with negative score get coef 0
    for (int t = tid; t < EXCL; t += 1024) {
        unsigned long long k64 = keys[t];
        unsigned int hi = (unsigned int)(k64 >> 32);
        if (hi < 0x80000000u) {   // decoded value < 0
            unsigned int idx = 0xFFFFFFFFu - (unsigned int)(k64 & 0xFFFFFFFFu);
            sc[idx] = 0.0f;
        }
    }
    __syncthreads();

    // g[f] = (1/k) * sum_i coef_i * X2[i][f]
    float acc = 0.f;
    for (int i = w; i < NN; i += 32) acc += sc[i] * X2[i * FF + lane];
    __syncthreads();                 // keys reads done; safe to reuse as scratch
    float* part = (float*)keys;
    part[w * FF + lane] = acc;
    __syncthreads();
    if (w == 0) {
        float gsum = 0.f;
#pragma unroll
        for (int q = 0; q < 32; ++q) gsum += part[q * FF + lane];
        sg[lane] = gsum / KSEL;
    }
    __syncthreads();
    if (tid < 8) {
        float a2 = lb[tid];
#pragma unroll
        for (int f = 0; f < FF; ++f) a2 += sg[f] * lw[tid * FF + f];
        out[tid] = a2;
    }
}

// ---------------- host side ----------------
static void run_conv(const float* xin_ext, int in_sel,
                     const float* Wr, const float* Wa, const float* Wb, int out_sel) {
    dim3 g(375), b(256);
    // order 0
    k_bjac<<<g, b>>>(xin_ext, in_sel, 4);
    k_jac<<<g, b>>>(4, 4, 5);
    k_jac<<<g, b>>>(5, 4, 6);
    k_jac<<<g, b>>>(6, 4, 5);
    k_jac<<<g, b>>>(5, 4, 6);
    k_jac<<<g, b>>>(6, 4, 2);   // -> Y1
    // order 1
    k_bjac<<<g, b>>>(nullptr, 2, 4);
    k_jac<<<g, b>>>(4, 4, 5);
    k_jac<<<g, b>>>(5, 4, 6);
    k_jac<<<g, b>>>(6, 4, 5);
    k_jac<<<g, b>>>(5, 4, 6);
    k_jac<<<g, b>>>(6, 4, 3);   // -> Y2
    k_outgemm<<<g, b>>>(xin_ext, in_sel, Wr, Wa, Wb, out_sel);
}

extern "C" void kernel_launch(void* const* d_in, const int* in_sizes, int n_in,
                              void* d_out, int out_size) {
    const float* x     = (const float*)d_in[0];
    const int*   ei    = (const int*)d_in[1];
    const int*   row   = ei;
    const int*   col   = ei + EE;
    const float* h     = (const float*)d_in[2];
    const float* alpha = (const float*)d_in[3];
    const float* Wr0   = (const float*)d_in[4];
    const float* Wc0a  = (const float*)d_in[5];
    const float* Wc0b  = (const float*)d_in[6];
    const float* Wr1   = (const float*)d_in[7];
    const float* Wc1a  = (const float*)d_in[8];
    const float* Wc1b  = (const float*)d_in[9];
    const float* pw    = (const float*)d_in[10];
    const float* lw    = (const float*)d_in[11];
    const float* lb    = (const float*)d_in[12];

    k_zero<<<(BM_WORDS + 255) / 256, 256>>>();
    k_edges<<<(EE + 255) / 256, 256>>>(row, col);
    k_scan<<<1, 1024>>>(h, alpha);
    k_scatter<<<(EE + 255) / 256, 256>>>(row, col);

    run_conv(x, -1, Wr0, Wc0a, Wc0b, 0);          // conv0 -> X1 (bufs[0])
    run_conv(nullptr, 0, Wr1, Wc1a, Wc1b, 1);     // conv1 -> X2 (bufs[1])

    k_final<<<1, 1024>>>(pw, lw, lb, (float*)d_out);
}

// round 2
// speedup vs baseline: 1.2632x; 1.2632x over previous
#include <cuda_runtime.h>
#include <math.h>

#define NN 3000
#define EE 48000
#define FF 32
#define BM_WORDS 281250   // ceil(3000*3000/32)
#define EXCL 1200
#define KSEL 10800.0f
#define GRID 148
#define TPB 1024
#define NWARPS (GRID * (TPB / 32))   // 4736

// ---------------- static device scratch ----------------
__device__ unsigned int g_bitmap[BM_WORDS];
__device__ int   g_deg[NN];
__device__ int   g_ucnt[NN];
__device__ int   g_rowptr[NN + 1];
__device__ int   g_cursor[NN];
__device__ unsigned char g_keep[EE];
__device__ int   g_colidx[EE];
__device__ float g_wv[EE];        // invD[col] folded into J weights
__device__ float g_sinv[NN];
__device__ float g_invD[NN];
// 0=X1, 1=X2, 2=Y1, 3=Y2, 4=BJ, 5=TA, 6=TB
__device__ float g_bufs[7][NN * FF];
__device__ float g_scf[NN];
__device__ unsigned long long g_keys[NN];
__device__ float g_part[GRID * FF];

__device__ unsigned int g_bar_arrive;          // self-resetting
__device__ volatile unsigned int g_bar_gen;    // monotonically increasing

__device__ __forceinline__ void grid_sync() {
    __syncthreads();
    if (threadIdx.x == 0) {
        __threadfence();                       // release: publish this block's writes
        unsigned int gen = g_bar_gen;
        if (atomicAdd(&g_bar_arrive, 1u) == (unsigned)(GRID - 1)) {
            g_bar_arrive = 0u;
            __threadfence();
            g_bar_gen = gen + 1u;
        } else {
            while (g_bar_gen == gen) { }
        }
        __threadfence();                       // acquire
    }
    __syncthreads();
}

__device__ __forceinline__ unsigned int f2ord(float f) {
    unsigned int u = __float_as_uint(f);
    return (u & 0x80000000u) ? ~u : (u | 0x80000000u);
}

// ---------------- SpMM phase helpers (warp per row, lane per feature) ----------------
__device__ __forceinline__ void phase_bjac(const float* __restrict__ yin,
                                           float* __restrict__ out, int wg, int lane) {
    for (int i = wg; i < NN; i += NWARPS) {
        int p0 = g_rowptr[i], p1 = g_rowptr[i + 1];
        float acc = 0.f;
        for (int p = p0; p < p1; ++p)
            acc += yin[g_colidx[p] * FF + lane];
        out[i * FF + lane] = yin[i * FF + lane] - g_sinv[i] * acc;
    }
}

__device__ __forceinline__ void phase_jac(const float* __restrict__ yk,
                                          const float* __restrict__ bj,
                                          float* __restrict__ out, int wg, int lane) {
    for (int i = wg; i < NN; i += NWARPS) {
        int p0 = g_rowptr[i], p1 = g_rowptr[i + 1];
        float acc = 0.f;
        for (int p = p0; p < p1; ++p)
            acc += g_wv[p] * yk[g_colidx[p] * FF + lane];
        out[i * FF + lane] = acc + bj[i * FF + lane];
    }
}

// ---------------- the one persistent kernel ----------------
__global__ void __launch_bounds__(TPB, 1)
cayley_all(const float* __restrict__ x, const int* __restrict__ ei,
           const float* __restrict__ ph, const float* __restrict__ palpha,
           const float* __restrict__ Wr0, const float* __restrict__ Wc0a,
           const float* __restrict__ Wc0b, const float* __restrict__ Wr1,
           const float* __restrict__ Wc1a, const float* __restrict__ Wc1b,
           const float* __restrict__ pw, const float* __restrict__ lw,
           const float* __restrict__ lb, float* __restrict__ out) {
    __shared__ unsigned long long s_u64[3008];   // 24 KB, aliased per phase

    const int tid  = threadIdx.x;
    const int gtid = blockIdx.x * TPB + tid;
    const int lane = tid & 31;
    const int wid  = tid >> 5;
    const int wg   = blockIdx.x * (TPB / 32) + wid;
    const int GSTRIDE = GRID * TPB;

    const int* row = ei;
    const int* col = ei + EE;

    // ---- P0: zero ----
    for (int i = gtid; i < BM_WORDS; i += GSTRIDE) g_bitmap[i] = 0u;
    for (int i = gtid; i < NN; i += GSTRIDE) { g_deg[i] = 0; g_ucnt[i] = 0; }
    grid_sync();

    // ---- P1: edge dedup + degree ----
    for (int e = gtid; e < EE; e += GSTRIDE) {
        int r = row[e], c = col[e];
        atomicAdd(&g_deg[r], 1);
        unsigned int bitpos = (unsigned int)(r * NN + c);
        unsigned int w = bitpos >> 5, b = 1u << (bitpos & 31);
        unsigned int old = atomicOr(&g_bitmap[w], b);
        unsigned char keep = (old & b) ? 0 : 1;
        g_keep[e] = keep;
        if (keep) atomicAdd(&g_ucnt[r], 1);
    }
    grid_sync();

    // ---- P2: per-node scalars + (block 0) prefix scan -> CSR rowptr ----
    {
        float h = *ph, alpha = *palpha;
        for (int i = gtid; i < NN; i += GSTRIDE) {
            float dv = (float)g_deg[i] - alpha;
            g_sinv[i] = 1.0f / dv;
            g_invD[i] = 1.0f / (dv * h);
        }
        if (blockIdx.x == 0) {
            int* loc  = (int*)s_u64;       // 3072 ints
            int* part = loc + 3072;        // 1024 ints (16 KB total < 24 KB)
            for (int i = tid; i < NN; i += TPB) loc[i] = g_ucnt[i];
            for (int i = NN + tid; i < 3072; i += TPB) loc[i] = 0;
            __syncthreads();
            int base = 3 * tid;
            int a0 = loc[base], a1 = loc[base + 1], a2 = loc[base + 2];
            part[tid] = a0 + a1 + a2;
            __syncthreads();
            for (int off = 1; off < TPB; off <<= 1) {
                int v = part[tid];
                int ad = (tid >= off) ? part[tid - off] : 0;
                __syncthreads();
                part[tid] = v + ad;
                __syncthreads();
            }
            int excl = (tid == 0) ? 0 : part[tid - 1];
            if (base < NN)     { g_rowptr[base]     = excl;           g_cursor[base]     = excl; }
            if (base + 1 < NN) { g_rowptr[base + 1] = excl + a0;      g_cursor[base + 1] = excl + a0; }
            if (base + 2 < NN) { g_rowptr[base + 2] = excl + a0 + a1; g_cursor[base + 2] = excl + a0 + a1; }
            if (tid == TPB - 1) g_rowptr[NN] = part[TPB - 1];
        }
    }
    grid_sync();

    // ---- P3: scatter edges into CSR ----
    for (int e = gtid; e < EE; e += GSTRIDE) {
        if (!g_keep[e]) continue;
        int r = row[e], c = col[e];
        int pos = atomicAdd(&g_cursor[r], 1);
        g_colidx[pos] = c;
        g_wv[pos] = g_invD[c];
    }
    grid_sync();

    // ---- two CayleyConv layers ----
    const float* Wrs[2]  = { Wr0,  Wr1 };
    const float* Was[2]  = { Wc0a, Wc1a };
    const float* Wbs[2]  = { Wc0b, Wc1b };

    for (int layer = 0; layer < 2; ++layer) {
        const float* X = (layer == 0) ? x : g_bufs[0];
        float* Xout = g_bufs[layer];   // layer0 -> X1 (buf0), layer1 -> X2 (buf1)

        for (int ord = 0; ord < 2; ++ord) {
            const float* Y = (ord == 0) ? X : g_bufs[2];
            // b_j -> buf4 (also serves as yk0)
            phase_bjac(Y, g_bufs[4], wg, lane);
            grid_sync();
            phase_jac(g_bufs[4], g_bufs[4], g_bufs[5], wg, lane); grid_sync();
            phase_jac(g_bufs[5], g_bufs[4], g_bufs[6], wg, lane); grid_sync();
            phase_jac(g_bufs[6], g_bufs[4], g_bufs[5], wg, lane); grid_sync();
            phase_jac(g_bufs[5], g_bufs[4], g_bufs[6], wg, lane); grid_sync();
            phase_jac(g_bufs[6], g_bufs[4], g_bufs[2 + ord], wg, lane); grid_sync();
        }

        // out = relu(X Wr^T + 2 Y1 Wca^T + 2 Y2 Wcb^T)
        {
            float* sW = (float*)s_u64;     // 3*1024 floats = 12 KB
            const float* Wr = Wrs[layer];
            const float* Wa = Was[layer];
            const float* Wb = Wbs[layer];
            for (int t = tid; t < FF * FF; t += TPB) {
                int f = t >> 5, k = t & 31;           // W[f][k] -> transposed
                sW[k * FF + f]             = Wr[t];
                sW[1024 + k * FF + f]      = Wa[t];
                sW[2048 + k * FF + f]      = Wb[t];
            }
            __syncthreads();
            const float* Y1 = g_bufs[2];
            const float* Y2 = g_bufs[3];
            for (int i = wg; i < NN; i += NWARPS) {
                float xo  = X[i * FF + lane];
                float y1o = Y1[i * FF + lane];
                float y2o = Y2[i * FF + lane];
                float acc = 0.f;
#pragma unroll
                for (int k = 0; k < FF; ++k) {
                    float xv  = __shfl_sync(0xffffffffu, xo, k);
                    float y1v = __shfl_sync(0xffffffffu, y1o, k);
                    float y2v = __shfl_sync(0xffffffffu, y2o, k);
                    acc += xv * sW[k * FF + lane]
                         + 2.0f * y1v * sW[1024 + k * FF + lane]
                         + 2.0f * y2v * sW[2048 + k * FF + lane];
                }
                Xout[i * FF + lane] = fmaxf(acc, 0.0f);
            }
        }
        grid_sync();
    }

    // ---- finale ----
    const float* X2 = g_bufs[1];

    // scores + sort keys (ascending: value, then larger index first)
    {
        float pwv = pw[lane];
        float nv = pwv * pwv;
#pragma unroll
        for (int o = 16; o > 0; o >>= 1) nv += __shfl_xor_sync(0xffffffffu, nv, o);
        float norm = sqrtf(nv);
        for (int i = wg; i < NN; i += NWARPS) {
            float v = X2[i * FF + lane] * pwv;
#pragma unroll
            for (int o = 16; o > 0; o >>= 1) v += __shfl_xor_sync(0xffffffffu, v, o);
            float s = tanhf(v / norm);
            if (lane == 0) {
                g_scf[i] = s;
                g_keys[i] = ((unsigned long long)f2ord(s) << 32)
                          | (unsigned long long)(0xFFFFFFFFu - (unsigned int)i);
            }
        }
    }
    grid_sync();

    // parallel rank: node excluded iff rank among real keys < 1200 AND score < 0
    {
        for (int i = tid; i < NN; i += TPB) s_u64[i] = g_keys[i];
        __syncthreads();
        for (int i = wg; i < NN; i += NWARPS) {
            unsigned long long ki = s_u64[i];
            int cnt = 0;
            for (int j = lane; j < NN; j += 32)
                cnt += (s_u64[j] < ki) ? 1 : 0;
#pragma unroll
            for (int o = 16; o > 0; o >>= 1) cnt += __shfl_xor_sync(0xffffffffu, cnt, o);
            if (lane == 0 && cnt < EXCL && (unsigned int)(ki >> 32) < 0x80000000u)
                g_scf[i] = 0.0f;
        }
    }
    grid_sync();

    // per-block partial weighted sums
    {
        float acc = 0.f;
        for (int i = wg; i < NN; i += NWARPS)
            acc += g_scf[i] * X2[i * FF + lane];
        float* sp = (float*)s_u64;
        sp[wid * FF + lane] = acc;
        __syncthreads();
        if (wid == 0) {
            float t = 0.f;
#pragma unroll
            for (int q = 0; q < 32; ++q) t += sp[q * FF + lane];
            g_part[blockIdx.x * FF + lane] = t;
        }
    }
    grid_sync();

    // block 0: reduce partials, pooled mean, final linear
    if (blockIdx.x == 0) {
        float* sp = (float*)s_u64;
        float a = 0.f;
        for (int b = wid; b < GRID; b += 32)
            a += g_part[b * FF + lane];
        sp[wid * FF + lane] = a;
        __syncthreads();
        if (wid == 0) {
            float t = 0.f;
#pragma unroll
            for (int q = 0; q < 32; ++q) t += sp[q * FF + lane];
            sp[1024 + lane] = t / KSEL;
        }
        __syncthreads();
        if (tid < 8) {
            float o = lb[tid];
#pragma unroll
            for (int f = 0; f < FF; ++f) o += sp[1024 + f] * lw[tid * FF + f];
            out[tid] = o;
        }
    }
}

// ---------------- host side ----------------
extern "C" void kernel_launch(void* const* d_in, const int* in_sizes, int n_in,
                              void* d_out, int out_size) {
    const float* x     = (const float*)d_in[0];
    const int*   ei    = (const int*)d_in[1];
    const float* h     = (const float*)d_in[2];
    const float* alpha = (const float*)d_in[3];
    const float* Wr0   = (const float*)d_in[4];
    const float* Wc0a  = (const float*)d_in[5];
    const float* Wc0b  = (const float*)d_in[6];
    const float* Wr1   = (const float*)d_in[7];
    const float* Wc1a  = (const float*)d_in[8];
    const float* Wc1b  = (const float*)d_in[9];
    const float* pw    = (const float*)d_in[10];
    const float* lw    = (const float*)d_in[11];
    const float* lb    = (const float*)d_in[12];

    cayley_all<<<GRID, TPB>>>(x, ei, h, alpha, Wr0, Wc0a, Wc0b,
                              Wr1, Wc1a, Wc1b, pw, lw, lb, (float*)d_out);
}